// round 1
// baseline (speedup 1.0000x reference)
#include <cuda_runtime.h>
#include <math.h>

#define BB 4
#define LL 4096
#define DD 256
#define AA 64
#define NROWS (BB*LL)

#define BM 64
#define BN 64
#define PAD 68   // row stride (floats): multiple of 4 for float4 alignment, odd-ish mod 32 for banks

// Scratch for projected Q, K, V (device globals: allocation rules forbid cudaMalloc)
__device__ float g_q[NROWS * AA];
__device__ float g_k[NROWS * AA];
__device__ float g_v[NROWS * AA];

// ---------------------------------------------------------------------------
// Kernel 1: QKV projection.  out[r][a] = sum_d x[r][d] * W[d][a]
// grid = (NROWS/64, 3), block = 256.  blockIdx.y selects Wq/Wk/Wv -> g_q/g_k/g_v.
// Tiled over D in chunks of 64; smem holds x chunk transposed (dim-major) and W chunk.
// ---------------------------------------------------------------------------
__global__ __launch_bounds__(256, 2)
void qkv_kernel(const float* __restrict__ x,
                const float* __restrict__ Wq,
                const float* __restrict__ Wk,
                const float* __restrict__ Wv) {
    __shared__ float xsT[64 * PAD];  // xsT[d][r]
    __shared__ float ws [64 * PAD];  // ws[d][a]

    const int row0 = blockIdx.x * 64;
    const int mat  = blockIdx.y;
    const float* W = (mat == 0) ? Wq : (mat == 1) ? Wk : Wv;
    float* dst     = (mat == 0) ? g_q : (mat == 1) ? g_k : g_v;

    const int tid = threadIdx.x;
    const int r0 = (tid >> 4) * 4;    // 16 row-groups of 4
    const int c0 = (tid & 15) * 4;    // 16 col-groups of 4

    float acc[4][4] = {};

    for (int d0 = 0; d0 < DD; d0 += 64) {
        __syncthreads();
        // load x chunk transposed: 64 rows x 64 dims
        {
            int r  = tid >> 6;        // 0..3
            int dd = tid & 63;
            #pragma unroll
            for (int rr = r; rr < 64; rr += 4)
                xsT[dd * PAD + rr] = x[(size_t)(row0 + rr) * DD + d0 + dd];
        }
        // load W chunk: 64 dims x 64 cols
        {
            int dd = tid >> 6;
            int a  = tid & 63;
            #pragma unroll
            for (int d = dd; d < 64; d += 4)
                ws[d * PAD + a] = W[(size_t)(d0 + d) * AA + a];
        }
        __syncthreads();

        #pragma unroll 8
        for (int kk = 0; kk < 64; ++kk) {
            float4 av = *(const float4*)&xsT[kk * PAD + r0];
            float4 bv = *(const float4*)&ws [kk * PAD + c0];
            float a_[4] = {av.x, av.y, av.z, av.w};
            float b_[4] = {bv.x, bv.y, bv.z, bv.w};
            #pragma unroll
            for (int i = 0; i < 4; ++i)
                #pragma unroll
                for (int j = 0; j < 4; ++j)
                    acc[i][j] += a_[i] * b_[j];
        }
    }

    #pragma unroll
    for (int i = 0; i < 4; ++i) {
        float4 v = make_float4(acc[i][0], acc[i][1], acc[i][2], acc[i][3]);
        *(float4*)&dst[(size_t)(row0 + r0 + i) * AA + c0] = v;
    }
}

// ---------------------------------------------------------------------------
// Kernel 2: causal flash attention, fp32 SIMT.
// grid = (L/BM, B), block = 256 threads.  Each block owns 64 query rows.
// smem: qsT[d][r], ksT[d][key], vs[key][d], psT[key][row] + per-row m/l/scale.
// Both matmuls are outer-product form: 2x LDS.128 per 16 FFMA.
// ---------------------------------------------------------------------------
__global__ __launch_bounds__(256, 2)
void attn_kernel(float* __restrict__ out) {
    extern __shared__ float sm[];
    float* qsT = sm;                  // [64][PAD]  dim-major Q
    float* ksT = qsT + 64 * PAD;      // [64][PAD]  dim-major K
    float* vs  = ksT + 64 * PAD;      // [64][PAD]  key-major V
    float* psT = vs  + 64 * PAD;      // [64][PAD]  key-major scores/probs (psT[key][row])
    float* rowm     = psT + 64 * PAD; // [64]
    float* rowl     = rowm + 64;      // [64]
    float* rowscale = rowl + 64;      // [64]

    const int b  = blockIdx.y;
    const int qt = blockIdx.x;
    const int q0 = qt * BM;
    const int tid = threadIdx.x;
    const int r0 = (tid >> 4) * 4;
    const int c0 = (tid & 15) * 4;

    // Load Q tile transposed (dim-major)
    {
        const float* qptr = g_q + ((size_t)b * LL + q0) * AA;
        for (int i = tid; i < BM * AA; i += 256) {
            int r = i >> 6, d = i & 63;
            qsT[d * PAD + r] = qptr[(size_t)r * AA + d];
        }
    }
    if (tid < 64) { rowm[tid] = -INFINITY; rowl[tid] = 0.f; }

    float acc[4][4] = {};

    for (int kt = 0; kt <= qt; ++kt) {
        const int k0 = kt * BN;
        __syncthreads();   // protect ks/vs/psT reuse from previous iteration

        // Load K (transposed) and V tiles
        {
            const float* kptr = g_k + ((size_t)b * LL + k0) * AA;
            const float* vptr = g_v + ((size_t)b * LL + k0) * AA;
            for (int i = tid; i < BN * AA; i += 256) {
                int r = i >> 6, d = i & 63;
                ksT[d * PAD + r] = kptr[i];
                vs [r * PAD + d] = vptr[i];
            }
        }
        __syncthreads();

        // S^T[key][row] = Q . K^T
        {
            float s[4][4] = {};
            #pragma unroll 8
            for (int kk = 0; kk < 64; ++kk) {
                float4 qv = *(const float4*)&qsT[kk * PAD + r0];
                float4 kv = *(const float4*)&ksT[kk * PAD + c0];
                float a_[4] = {qv.x, qv.y, qv.z, qv.w};
                float b_[4] = {kv.x, kv.y, kv.z, kv.w};
                #pragma unroll
                for (int i = 0; i < 4; ++i)
                    #pragma unroll
                    for (int j = 0; j < 4; ++j)
                        s[i][j] += a_[i] * b_[j];
            }
            #pragma unroll
            for (int j = 0; j < 4; ++j)
                #pragma unroll
                for (int i = 0; i < 4; ++i)
                    psT[(c0 + j) * PAD + (r0 + i)] = s[i][j];
        }
        __syncthreads();

        // Online softmax: one thread per query row; psT column reads are
        // conflict-free (addresses r + 68*c across lanes).
        if (tid < 64) {
            const int r  = tid;
            const int qg = q0 + r;
            int kmax = qg - k0 + 1;           // valid keys in this tile
            if (kmax > BN) kmax = BN;
            float m_old = rowm[r];
            float m = m_old;
            for (int c = 0; c < kmax; ++c)
                m = fmaxf(m, psT[c * PAD + r]);
            float corr = (m_old == -INFINITY) ? 0.f : __expf(m_old - m);
            float lsum = 0.f;
            for (int c = 0; c < BN; ++c) {
                float p = (c < kmax) ? __expf(psT[c * PAD + r] - m) : 0.f;
                psT[c * PAD + r] = p;
                lsum += p;
            }
            rowl[r] = rowl[r] * corr + lsum;
            rowm[r] = m;
            rowscale[r] = corr;
        }
        __syncthreads();

        // O = O*diag(corr) + P . V
        {
            float sc[4];
            #pragma unroll
            for (int i = 0; i < 4; ++i) sc[i] = rowscale[r0 + i];
            #pragma unroll
            for (int i = 0; i < 4; ++i)
                #pragma unroll
                for (int j = 0; j < 4; ++j)
                    acc[i][j] *= sc[i];

            #pragma unroll 8
            for (int kk = 0; kk < 64; ++kk) {
                float4 pv = *(const float4*)&psT[kk * PAD + r0];
                float4 vv = *(const float4*)&vs [kk * PAD + c0];
                float a_[4] = {pv.x, pv.y, pv.z, pv.w};
                float b_[4] = {vv.x, vv.y, vv.z, vv.w};
                #pragma unroll
                for (int i = 0; i < 4; ++i)
                    #pragma unroll
                    for (int j = 0; j < 4; ++j)
                        acc[i][j] += a_[i] * b_[j];
            }
        }
    }

    // Epilogue: normalize and store (rowl final values synced by last O-update barrier)
    float* optr = out + ((size_t)b * LL + q0) * AA;
    #pragma unroll
    for (int i = 0; i < 4; ++i) {
        float inv = 1.f / rowl[r0 + i];
        float4 v = make_float4(acc[i][0] * inv, acc[i][1] * inv,
                               acc[i][2] * inv, acc[i][3] * inv);
        *(float4*)&optr[(size_t)(r0 + i) * AA + c0] = v;
    }
}

// ---------------------------------------------------------------------------
extern "C" void kernel_launch(void* const* d_in, const int* in_sizes, int n_in,
                              void* d_out, int out_size) {
    (void)in_sizes; (void)n_in; (void)out_size;
    const float* x  = (const float*)d_in[0];
    const float* Wq = (const float*)d_in[1];
    const float* Wk = (const float*)d_in[2];
    const float* Wv = (const float*)d_in[3];
    float* out = (float*)d_out;

    // QKV projection
    {
        dim3 grid(NROWS / 64, 3);
        qkv_kernel<<<grid, 256>>>(x, Wq, Wk, Wv);
    }

    // Flash attention
    {
        size_t smem = (size_t)(4 * 64 * PAD + 3 * 64) * sizeof(float);  // ~70.4 KB
        cudaFuncSetAttribute(attn_kernel, cudaFuncAttributeMaxDynamicSharedMemorySize, (int)smem);
        dim3 grid(LL / BM, BB);
        attn_kernel<<<grid, 256, smem>>>(out);
    }
}

// round 2
// speedup vs baseline: 2.3098x; 2.3098x over previous
#include <cuda_runtime.h>
#include <cuda_bf16.h>
#include <math.h>

#define BB 4
#define LL 4096
#define DD 256
#define AA 64
#define NROWS (BB*LL)
#define NPAIR 32           // 64 elems -> 32 bf16x2 pairs
#define TSTRIDE 36         // smem tile row stride in u32 (conflict-free frag loads)
#define PAD 68

// Packed bf16 hi/lo splits (precomputed by projection kernel)
__device__ unsigned int g_qhi[NROWS*NPAIR], g_qlo[NROWS*NPAIR];
__device__ unsigned int g_khi[NROWS*NPAIR], g_klo[NROWS*NPAIR];
__device__ unsigned int g_vthi[BB*AA*(LL/2)], g_vtlo[BB*AA*(LL/2)];  // [b][d][keypair]

// ---------------------------------------------------------------------------
// bf16 hi/lo split of a float pair, packed into bf16x2 words (f0 in low half)
// ---------------------------------------------------------------------------
__device__ __forceinline__ void split2(float f0, float f1, unsigned &hi, unsigned &lo) {
    unsigned short h0 = __bfloat16_as_ushort(__float2bfloat16_rn(f0));
    unsigned short h1 = __bfloat16_as_ushort(__float2bfloat16_rn(f1));
    float r0 = f0 - __bfloat162float(__ushort_as_bfloat16(h0));
    float r1 = f1 - __bfloat162float(__ushort_as_bfloat16(h1));
    unsigned short e0 = __bfloat16_as_ushort(__float2bfloat16_rn(r0));
    unsigned short e1 = __bfloat16_as_ushort(__float2bfloat16_rn(r1));
    hi = (unsigned)h0 | ((unsigned)h1 << 16);
    lo = (unsigned)e0 | ((unsigned)e1 << 16);
}

// m16n8k16 bf16 mma, D += A*B (C==D accumulate in fp32)
__device__ __forceinline__ void mma_bf16(float (&d)[4], const unsigned (&a)[4],
                                         unsigned b0, unsigned b1) {
    asm volatile(
        "mma.sync.aligned.m16n8k16.row.col.f32.bf16.bf16.f32 "
        "{%0,%1,%2,%3}, {%4,%5,%6,%7}, {%8,%9}, {%0,%1,%2,%3};"
        : "+f"(d[0]), "+f"(d[1]), "+f"(d[2]), "+f"(d[3])
        : "r"(a[0]), "r"(a[1]), "r"(a[2]), "r"(a[3]), "r"(b0), "r"(b1));
}

// ---------------------------------------------------------------------------
// Kernel 1: QKV projection (fp32 SIMT, exact), emits packed bf16 hi/lo splits.
// grid = (NROWS/64, 3), block = 256.
// ---------------------------------------------------------------------------
__global__ __launch_bounds__(256, 2)
void qkv_kernel(const float* __restrict__ x,
                const float* __restrict__ Wq,
                const float* __restrict__ Wk,
                const float* __restrict__ Wv) {
    __shared__ float xsT[64 * PAD];  // xsT[d][r]
    __shared__ float ws [64 * PAD];  // ws[d][a]

    const int row0 = blockIdx.x * 64;
    const int mat  = blockIdx.y;
    const float* W = (mat == 0) ? Wq : (mat == 1) ? Wk : Wv;

    const int tid = threadIdx.x;
    const int r0 = (tid >> 4) * 4;
    const int c0 = (tid & 15) * 4;

    float acc[4][4] = {};

    for (int d0 = 0; d0 < DD; d0 += 64) {
        __syncthreads();
        {
            int r  = tid >> 6;
            int dd = tid & 63;
            #pragma unroll
            for (int rr = r; rr < 64; rr += 4)
                xsT[dd * PAD + rr] = x[(size_t)(row0 + rr) * DD + d0 + dd];
        }
        {
            int dd = tid >> 6;
            int a  = tid & 63;
            #pragma unroll
            for (int d = dd; d < 64; d += 4)
                ws[d * PAD + a] = W[(size_t)(d0 + d) * AA + a];
        }
        __syncthreads();

        #pragma unroll 8
        for (int kk = 0; kk < 64; ++kk) {
            float4 av = *(const float4*)&xsT[kk * PAD + r0];
            float4 bv = *(const float4*)&ws [kk * PAD + c0];
            float a_[4] = {av.x, av.y, av.z, av.w};
            float b_[4] = {bv.x, bv.y, bv.z, bv.w};
            #pragma unroll
            for (int i = 0; i < 4; ++i)
                #pragma unroll
                for (int j = 0; j < 4; ++j)
                    acc[i][j] += a_[i] * b_[j];
        }
    }

    if (mat < 2) {
        // Q/K: row-major, pairs along the A dim
        unsigned* dh = (mat == 0) ? g_qhi : g_khi;
        unsigned* dl = (mat == 0) ? g_qlo : g_klo;
        #pragma unroll
        for (int i = 0; i < 4; ++i) {
            size_t base = (size_t)(row0 + r0 + i) * NPAIR + (c0 >> 1);
            unsigned h, l;
            split2(acc[i][0], acc[i][1], h, l); dh[base]   = h; dl[base]   = l;
            split2(acc[i][2], acc[i][3], h, l); dh[base+1] = h; dl[base+1] = l;
        }
    } else {
        // V: transposed [b][d][keypair]
        int R0 = row0 + r0;
        int bb = R0 / LL;
        int lr = R0 % LL;
        #pragma unroll
        for (int j = 0; j < 4; ++j) {
            int d = c0 + j;
            size_t base = (size_t)(bb * AA + d) * (LL/2) + (lr >> 1);
            unsigned h, l;
            split2(acc[0][j], acc[1][j], h, l); g_vthi[base]   = h; g_vtlo[base]   = l;
            split2(acc[2][j], acc[3][j], h, l); g_vthi[base+1] = h; g_vtlo[base+1] = l;
        }
    }
}

// ---------------------------------------------------------------------------
// Kernel 2: causal flash attention on tensor cores (bf16 3-term split mma).
// grid = 256 (longest jobs first), block = 128 (4 warps, each owns 16 q-rows
// across the full 64-key tile -> softmax fully in registers + quad shuffles).
// ---------------------------------------------------------------------------
__global__ __launch_bounds__(128)
void attn_kernel(float* __restrict__ out) {
    extern __shared__ unsigned smbuf[];
    unsigned* Qh = smbuf;
    unsigned* Ql = Qh + 64 * TSTRIDE;
    unsigned* Kh = Ql + 64 * TSTRIDE;
    unsigned* Kl = Kh + 64 * TSTRIDE;
    unsigned* Vh = Kl + 64 * TSTRIDE;
    unsigned* Vl = Vh + 64 * TSTRIDE;
    unsigned* Ph = Vl + 64 * TSTRIDE;
    unsigned* Pl = Ph + 64 * TSTRIDE;

    const int gx  = blockIdx.x;
    const int qt  = 63 - (gx >> 2);      // longest-first (LPT) ordering
    const int b   = gx & 3;
    const int q0  = qt * 64;
    const int tid = threadIdx.x;
    const int wid = tid >> 5;
    const int lane = tid & 31;
    const int g   = lane >> 2;           // 0..7
    const int tig = lane & 3;            // 0..3
    const int g0  = wid * 16;            // warp's query-row strip

    const int cr = tid >> 1;             // copy row 0..63
    const int ch = (tid & 1) * 16;       // copy half

    // Load Q tile (packed hi/lo)
    {
        const uint4* sh = (const uint4*)&g_qhi[(size_t)(b*LL + q0 + cr) * NPAIR + ch];
        const uint4* sl = (const uint4*)&g_qlo[(size_t)(b*LL + q0 + cr) * NPAIR + ch];
        uint4* dh = (uint4*)&Qh[cr * TSTRIDE + ch];
        uint4* dl = (uint4*)&Ql[cr * TSTRIDE + ch];
        #pragma unroll
        for (int i = 0; i < 4; ++i) { dh[i] = sh[i]; dl[i] = sl[i]; }
    }

    float o[8][4] = {};
    float m0 = -INFINITY, m1 = -INFINITY, l0 = 0.f, l1 = 0.f;

    for (int kt = 0; kt <= qt; ++kt) {
        const int k0 = kt * 64;
        __syncthreads();  // previous tile's smem reads complete

        // Load K tile (row-major pairs) and V tile ([d][keypair])
        {
            const uint4* skh = (const uint4*)&g_khi [(size_t)(b*LL + k0 + cr) * NPAIR + ch];
            const uint4* skl = (const uint4*)&g_klo [(size_t)(b*LL + k0 + cr) * NPAIR + ch];
            const uint4* svh = (const uint4*)&g_vthi[(size_t)(b*AA + cr) * (LL/2) + (k0>>1) + ch];
            const uint4* svl = (const uint4*)&g_vtlo[(size_t)(b*AA + cr) * (LL/2) + (k0>>1) + ch];
            uint4* dkh = (uint4*)&Kh[cr * TSTRIDE + ch];
            uint4* dkl = (uint4*)&Kl[cr * TSTRIDE + ch];
            uint4* dvh = (uint4*)&Vh[cr * TSTRIDE + ch];
            uint4* dvl = (uint4*)&Vl[cr * TSTRIDE + ch];
            #pragma unroll
            for (int i = 0; i < 4; ++i) {
                dkh[i] = skh[i]; dkl[i] = skl[i];
                dvh[i] = svh[i]; dvl[i] = svl[i];
            }
        }
        __syncthreads();

        // ---- S = Q . K^T  (16 rows x 64 keys per warp), 3-term bf16 split ----
        float s[8][4];
        #pragma unroll
        for (int sub = 0; sub < 8; ++sub)
            #pragma unroll
            for (int i = 0; i < 4; ++i) s[sub][i] = 0.f;

        #pragma unroll
        for (int ks = 0; ks < 4; ++ks) {
            unsigned ah[4], al[4];
            const int ar0 = (g0 + g) * TSTRIDE + ks * 8;
            const int ar1 = ar0 + 8 * TSTRIDE;
            ah[0] = Qh[ar0 + tig];     ah[1] = Qh[ar1 + tig];
            ah[2] = Qh[ar0 + tig + 4]; ah[3] = Qh[ar1 + tig + 4];
            al[0] = Ql[ar0 + tig];     al[1] = Ql[ar1 + tig];
            al[2] = Ql[ar0 + tig + 4]; al[3] = Ql[ar1 + tig + 4];
            #pragma unroll
            for (int sub = 0; sub < 8; ++sub) {
                const int br = (sub * 8 + g) * TSTRIDE + ks * 8;
                unsigned bh0 = Kh[br + tig], bh1 = Kh[br + tig + 4];
                unsigned bl0 = Kl[br + tig], bl1 = Kl[br + tig + 4];
                mma_bf16(s[sub], ah, bh0, bh1);
                mma_bf16(s[sub], ah, bl0, bl1);
                mma_bf16(s[sub], al, bh0, bh1);
            }
        }

        // Causal mask (diagonal tile only)
        if (kt == qt) {
            #pragma unroll
            for (int sub = 0; sub < 8; ++sub) {
                const int kc = sub * 8 + 2 * tig;
                const int r_lo = g0 + g, r_hi = r_lo + 8;
                if (kc     > r_lo) s[sub][0] = -INFINITY;
                if (kc + 1 > r_lo) s[sub][1] = -INFINITY;
                if (kc     > r_hi) s[sub][2] = -INFINITY;
                if (kc + 1 > r_hi) s[sub][3] = -INFINITY;
            }
        }

        // ---- online softmax, fully in registers (quad shuffles) ----
        float mt0 = -INFINITY, mt1 = -INFINITY;
        #pragma unroll
        for (int sub = 0; sub < 8; ++sub) {
            mt0 = fmaxf(mt0, fmaxf(s[sub][0], s[sub][1]));
            mt1 = fmaxf(mt1, fmaxf(s[sub][2], s[sub][3]));
        }
        mt0 = fmaxf(mt0, __shfl_xor_sync(0xffffffffu, mt0, 1));
        mt0 = fmaxf(mt0, __shfl_xor_sync(0xffffffffu, mt0, 2));
        mt1 = fmaxf(mt1, __shfl_xor_sync(0xffffffffu, mt1, 1));
        mt1 = fmaxf(mt1, __shfl_xor_sync(0xffffffffu, mt1, 2));

        const float mn0 = fmaxf(m0, mt0);
        const float mn1 = fmaxf(m1, mt1);
        const float c0f = __expf(m0 - mn0);   // 0 when m0 == -inf
        const float c1f = __expf(m1 - mn1);

        float sum0 = 0.f, sum1 = 0.f;
        const int prow0 = (g0 + g) * TSTRIDE;
        const int prow1 = prow0 + 8 * TSTRIDE;
        #pragma unroll
        for (int sub = 0; sub < 8; ++sub) {
            float p0 = __expf(s[sub][0] - mn0);
            float p1 = __expf(s[sub][1] - mn0);
            float p2 = __expf(s[sub][2] - mn1);
            float p3 = __expf(s[sub][3] - mn1);
            sum0 += p0 + p1;  sum1 += p2 + p3;
            unsigned h, l;
            split2(p0, p1, h, l); Ph[prow0 + sub*4 + tig] = h; Pl[prow0 + sub*4 + tig] = l;
            split2(p2, p3, h, l); Ph[prow1 + sub*4 + tig] = h; Pl[prow1 + sub*4 + tig] = l;
            o[sub][0] *= c0f; o[sub][1] *= c0f;
            o[sub][2] *= c1f; o[sub][3] *= c1f;
        }
        sum0 += __shfl_xor_sync(0xffffffffu, sum0, 1);
        sum0 += __shfl_xor_sync(0xffffffffu, sum0, 2);
        sum1 += __shfl_xor_sync(0xffffffffu, sum1, 1);
        sum1 += __shfl_xor_sync(0xffffffffu, sum1, 2);
        l0 = l0 * c0f + sum0;
        l1 = l1 * c1f + sum1;
        m0 = mn0; m1 = mn1;

        __syncthreads();  // P visible to all warps

        // ---- O += P . V  (16 rows x 64 dims per warp), 3-term bf16 split ----
        #pragma unroll
        for (int ks = 0; ks < 4; ++ks) {
            unsigned ah[4], al[4];
            const int ar0 = prow0 + ks * 8;
            const int ar1 = prow1 + ks * 8;
            ah[0] = Ph[ar0 + tig];     ah[1] = Ph[ar1 + tig];
            ah[2] = Ph[ar0 + tig + 4]; ah[3] = Ph[ar1 + tig + 4];
            al[0] = Pl[ar0 + tig];     al[1] = Pl[ar1 + tig];
            al[2] = Pl[ar0 + tig + 4]; al[3] = Pl[ar1 + tig + 4];
            #pragma unroll
            for (int sub = 0; sub < 8; ++sub) {
                const int br = (sub * 8 + g) * TSTRIDE + ks * 8;
                unsigned bh0 = Vh[br + tig], bh1 = Vh[br + tig + 4];
                unsigned bl0 = Vl[br + tig], bl1 = Vl[br + tig + 4];
                mma_bf16(o[sub], ah, bh0, bh1);
                mma_bf16(o[sub], ah, bl0, bl1);
                mma_bf16(o[sub], al, bh0, bh1);
            }
        }
    }

    // Epilogue: normalize and store
    const float inv0 = 1.f / l0;
    const float inv1 = 1.f / l1;
    float* base0 = out + ((size_t)(b * LL + q0 + g0 + g)) * AA;
    float* base1 = base0 + (size_t)8 * AA;
    #pragma unroll
    for (int sub = 0; sub < 8; ++sub) {
        const int dcol = sub * 8 + 2 * tig;
        *(float2*)&base0[dcol] = make_float2(o[sub][0] * inv0, o[sub][1] * inv0);
        *(float2*)&base1[dcol] = make_float2(o[sub][2] * inv1, o[sub][3] * inv1);
    }
}

// ---------------------------------------------------------------------------
extern "C" void kernel_launch(void* const* d_in, const int* in_sizes, int n_in,
                              void* d_out, int out_size) {
    (void)in_sizes; (void)n_in; (void)out_size;
    const float* x  = (const float*)d_in[0];
    const float* Wq = (const float*)d_in[1];
    const float* Wk = (const float*)d_in[2];
    const float* Wv = (const float*)d_in[3];
    float* out = (float*)d_out;

    {
        dim3 grid(NROWS / 64, 3);
        qkv_kernel<<<grid, 256>>>(x, Wq, Wk, Wv);
    }
    {
        size_t smem = (size_t)8 * 64 * TSTRIDE * sizeof(unsigned);  // 73728 B
        cudaFuncSetAttribute(attn_kernel, cudaFuncAttributeMaxDynamicSharedMemorySize, (int)smem);
        attn_kernel<<<256, 128, smem>>>(out);
    }
}

// round 4
// speedup vs baseline: 2.4780x; 1.0728x over previous
#include <cuda_runtime.h>
#include <cuda_bf16.h>
#include <math.h>

#define BB 4
#define LL 4096
#define DD 256
#define AA 64
#define NROWS (BB*LL)
#define NPAIR 32           // 64 elems -> 32 bf16x2 pairs
#define TSTRIDE 36         // smem tile row stride in u32 (conflict-free frag loads)
#define PAD 68

// Packed bf16 hi/lo splits (precomputed by projection kernel)
__device__ unsigned int g_qhi[NROWS*NPAIR], g_qlo[NROWS*NPAIR];
__device__ unsigned int g_khi[NROWS*NPAIR], g_klo[NROWS*NPAIR];
__device__ unsigned int g_vthi[BB*AA*(LL/2)], g_vtlo[BB*AA*(LL/2)];  // [b][d][keypair]

// ---------------------------------------------------------------------------
__device__ __forceinline__ void split2(float f0, float f1, unsigned &hi, unsigned &lo) {
    unsigned short h0 = __bfloat16_as_ushort(__float2bfloat16_rn(f0));
    unsigned short h1 = __bfloat16_as_ushort(__float2bfloat16_rn(f1));
    float r0 = f0 - __bfloat162float(__ushort_as_bfloat16(h0));
    float r1 = f1 - __bfloat162float(__ushort_as_bfloat16(h1));
    unsigned short e0 = __bfloat16_as_ushort(__float2bfloat16_rn(r0));
    unsigned short e1 = __bfloat16_as_ushort(__float2bfloat16_rn(r1));
    hi = (unsigned)h0 | ((unsigned)h1 << 16);
    lo = (unsigned)e0 | ((unsigned)e1 << 16);
}

__device__ __forceinline__ void mma_bf16(float (&d)[4], const unsigned (&a)[4],
                                         unsigned b0, unsigned b1) {
    asm volatile(
        "mma.sync.aligned.m16n8k16.row.col.f32.bf16.bf16.f32 "
        "{%0,%1,%2,%3}, {%4,%5,%6,%7}, {%8,%9}, {%0,%1,%2,%3};"
        : "+f"(d[0]), "+f"(d[1]), "+f"(d[2]), "+f"(d[3])
        : "r"(a[0]), "r"(a[1]), "r"(a[2]), "r"(a[3]), "r"(b0), "r"(b1));
}

__device__ __forceinline__ void cpa16(void* s, const void* g) {
    unsigned sa = (unsigned)__cvta_generic_to_shared(s);
    asm volatile("cp.async.cg.shared.global [%0], [%1], 16;" :: "r"(sa), "l"(g));
}

// ---------------------------------------------------------------------------
// Kernel 1: QKV projection (fp32 SIMT, exact), emits packed bf16 hi/lo splits.
// ---------------------------------------------------------------------------
__global__ __launch_bounds__(256, 2)
void qkv_kernel(const float* __restrict__ x,
                const float* __restrict__ Wq,
                const float* __restrict__ Wk,
                const float* __restrict__ Wv) {
    __shared__ float xsT[64 * PAD];
    __shared__ float ws [64 * PAD];

    const int row0 = blockIdx.x * 64;
    const int mat  = blockIdx.y;
    const float* W = (mat == 0) ? Wq : (mat == 1) ? Wk : Wv;

    const int tid = threadIdx.x;
    const int r0 = (tid >> 4) * 4;
    const int c0 = (tid & 15) * 4;

    float acc[4][4] = {};

    for (int d0 = 0; d0 < DD; d0 += 64) {
        __syncthreads();
        {
            int r  = tid >> 6;
            int dd = tid & 63;
            #pragma unroll
            for (int rr = r; rr < 64; rr += 4)
                xsT[dd * PAD + rr] = x[(size_t)(row0 + rr) * DD + d0 + dd];
        }
        {
            int dd = tid >> 6;
            int a  = tid & 63;
            #pragma unroll
            for (int d = dd; d < 64; d += 4)
                ws[d * PAD + a] = W[(size_t)(d0 + d) * AA + a];
        }
        __syncthreads();

        #pragma unroll 8
        for (int kk = 0; kk < 64; ++kk) {
            float4 av = *(const float4*)&xsT[kk * PAD + r0];
            float4 bv = *(const float4*)&ws [kk * PAD + c0];
            float a_[4] = {av.x, av.y, av.z, av.w};
            float b_[4] = {bv.x, bv.y, bv.z, bv.w};
            #pragma unroll
            for (int i = 0; i < 4; ++i)
                #pragma unroll
                for (int j = 0; j < 4; ++j)
                    acc[i][j] += a_[i] * b_[j];
        }
    }

    if (mat < 2) {
        unsigned* dh = (mat == 0) ? g_qhi : g_khi;
        unsigned* dl = (mat == 0) ? g_qlo : g_klo;
        #pragma unroll
        for (int i = 0; i < 4; ++i) {
            size_t base = (size_t)(row0 + r0 + i) * NPAIR + (c0 >> 1);
            unsigned h, l;
            split2(acc[i][0], acc[i][1], h, l); dh[base]   = h; dl[base]   = l;
            split2(acc[i][2], acc[i][3], h, l); dh[base+1] = h; dl[base+1] = l;
        }
    } else {
        int R0 = row0 + r0;
        int bb = R0 / LL;
        int lr = R0 % LL;
        #pragma unroll
        for (int j = 0; j < 4; ++j) {
            int d = c0 + j;
            size_t base = (size_t)(bb * AA + d) * (LL/2) + (lr >> 1);
            unsigned h, l;
            split2(acc[0][j], acc[1][j], h, l); g_vthi[base]   = h; g_vtlo[base]   = l;
            split2(acc[2][j], acc[3][j], h, l); g_vthi[base+1] = h; g_vtlo[base+1] = l;
        }
    }
}

// ---------------------------------------------------------------------------
// Kernel 2: causal flash attention on tensor cores.
// Q in registers, P in registers (C-frag -> A-frag), K/V double-buffered
// via cp.async.  grid = 256 (LPT order), block = 128.
// ---------------------------------------------------------------------------
#define TILE_U32 (64 * TSTRIDE)

__global__ __launch_bounds__(128)
void attn_kernel(float* __restrict__ out) {
    extern __shared__ unsigned smbuf[];
    // layout per buffer: Kh, Kl, Vh, Vl each TILE_U32
    const int gx  = blockIdx.x;
    const int qt  = 63 - (gx >> 2);
    const int b   = gx & 3;
    const int q0  = qt * 64;
    const int tid = threadIdx.x;
    const int wid = tid >> 5;
    const int lane = tid & 31;
    const int g   = lane >> 2;
    const int tig = lane & 3;
    const int g0  = wid * 16;

    // copy mapping for cp.async: each thread does 4x16B per array
    const int crow = tid >> 1;
    const int ccol = (tid & 1) * 16;

    // ---- Q fragments (loop-invariant) from gmem ----
    unsigned qh[4][4], ql[4][4];
    {
        const unsigned* qbh = g_qhi + (size_t)(b*LL + q0) * NPAIR;
        const unsigned* qbl = g_qlo + (size_t)(b*LL + q0) * NPAIR;
        const int ra = (g0 + g) * NPAIR;
        const int rb = ra + 8 * NPAIR;
        #pragma unroll
        for (int ks = 0; ks < 4; ++ks) {
            const int p0 = ks * 8 + tig;
            qh[ks][0] = qbh[ra + p0];     qh[ks][1] = qbh[rb + p0];
            qh[ks][2] = qbh[ra + p0 + 4]; qh[ks][3] = qbh[rb + p0 + 4];
            ql[ks][0] = qbl[ra + p0];     ql[ks][1] = qbl[rb + p0];
            ql[ks][2] = qbl[ra + p0 + 4]; ql[ks][3] = qbl[rb + p0 + 4];
        }
    }

    // ---- prefetch helper (macro-ish lambda) ----
    auto prefetch = [&](int bufsel, int k0) {
        unsigned* base = smbuf + bufsel * 4 * TILE_U32;
        unsigned* dkh = base                + crow * TSTRIDE + ccol;
        unsigned* dkl = base + 1*TILE_U32   + crow * TSTRIDE + ccol;
        unsigned* dvh = base + 2*TILE_U32   + crow * TSTRIDE + ccol;
        unsigned* dvl = base + 3*TILE_U32   + crow * TSTRIDE + ccol;
        const unsigned* skh = &g_khi [(size_t)(b*LL + k0 + crow) * NPAIR + ccol];
        const unsigned* skl = &g_klo [(size_t)(b*LL + k0 + crow) * NPAIR + ccol];
        const unsigned* svh = &g_vthi[(size_t)(b*AA + crow) * (LL/2) + (k0 >> 1) + ccol];
        const unsigned* svl = &g_vtlo[(size_t)(b*AA + crow) * (LL/2) + (k0 >> 1) + ccol];
        #pragma unroll
        for (int i = 0; i < 4; ++i) {
            cpa16(dkh + 4*i, skh + 4*i);
            cpa16(dkl + 4*i, skl + 4*i);
            cpa16(dvh + 4*i, svh + 4*i);
            cpa16(dvl + 4*i, svl + 4*i);
        }
        asm volatile("cp.async.commit_group;");
    };

    prefetch(0, 0);

    float o[8][4] = {};
    float m0 = -INFINITY, m1 = -INFINITY, l0 = 0.f, l1 = 0.f;

    for (int kt = 0; kt <= qt; ++kt) {
        if (kt < qt) {
            prefetch((kt + 1) & 1, (kt + 1) * 64);
            asm volatile("cp.async.wait_group 1;");
        } else {
            asm volatile("cp.async.wait_group 0;");
        }
        __syncthreads();

        const unsigned* base = smbuf + (kt & 1) * 4 * TILE_U32;
        const unsigned* Kh = base;
        const unsigned* Kl = base + 1*TILE_U32;
        const unsigned* Vh = base + 2*TILE_U32;
        const unsigned* Vl = base + 3*TILE_U32;

        // ---- S = Q . K^T ----
        float s[8][4];
        #pragma unroll
        for (int sub = 0; sub < 8; ++sub)
            #pragma unroll
            for (int i = 0; i < 4; ++i) s[sub][i] = 0.f;

        #pragma unroll
        for (int ks = 0; ks < 4; ++ks) {
            #pragma unroll
            for (int sub = 0; sub < 8; ++sub) {
                const int br = (sub * 8 + g) * TSTRIDE + ks * 8;
                unsigned bh0 = Kh[br + tig], bh1 = Kh[br + tig + 4];
                unsigned bl0 = Kl[br + tig], bl1 = Kl[br + tig + 4];
                mma_bf16(s[sub], qh[ks], bh0, bh1);
                mma_bf16(s[sub], qh[ks], bl0, bl1);
                mma_bf16(s[sub], ql[ks], bh0, bh1);
            }
        }

        // ---- causal mask (diagonal tile) ----
        if (kt == qt) {
            #pragma unroll
            for (int sub = 0; sub < 8; ++sub) {
                const int kc = sub * 8 + 2 * tig;
                const int r_lo = g0 + g, r_hi = r_lo + 8;
                if (kc     > r_lo) s[sub][0] = -INFINITY;
                if (kc + 1 > r_lo) s[sub][1] = -INFINITY;
                if (kc     > r_hi) s[sub][2] = -INFINITY;
                if (kc + 1 > r_hi) s[sub][3] = -INFINITY;
            }
        }

        // ---- online softmax (registers + quad shuffles) ----
        float mt0 = -INFINITY, mt1 = -INFINITY;
        #pragma unroll
        for (int sub = 0; sub < 8; ++sub) {
            mt0 = fmaxf(mt0, fmaxf(s[sub][0], s[sub][1]));
            mt1 = fmaxf(mt1, fmaxf(s[sub][2], s[sub][3]));
        }
        mt0 = fmaxf(mt0, __shfl_xor_sync(0xffffffffu, mt0, 1));
        mt0 = fmaxf(mt0, __shfl_xor_sync(0xffffffffu, mt0, 2));
        mt1 = fmaxf(mt1, __shfl_xor_sync(0xffffffffu, mt1, 1));
        mt1 = fmaxf(mt1, __shfl_xor_sync(0xffffffffu, mt1, 2));

        const float mn0 = fmaxf(m0, mt0);
        const float mn1 = fmaxf(m1, mt1);
        const float c0f = __expf(m0 - mn0);
        const float c1f = __expf(m1 - mn1);

        unsigned ph[8][2], pl[8][2];
        float sum0 = 0.f, sum1 = 0.f;
        #pragma unroll
        for (int sub = 0; sub < 8; ++sub) {
            float p0 = __expf(s[sub][0] - mn0);
            float p1 = __expf(s[sub][1] - mn0);
            float p2 = __expf(s[sub][2] - mn1);
            float p3 = __expf(s[sub][3] - mn1);
            sum0 += p0 + p1;  sum1 += p2 + p3;
            split2(p0, p1, ph[sub][0], pl[sub][0]);
            split2(p2, p3, ph[sub][1], pl[sub][1]);
            o[sub][0] *= c0f; o[sub][1] *= c0f;
            o[sub][2] *= c1f; o[sub][3] *= c1f;
        }
        sum0 += __shfl_xor_sync(0xffffffffu, sum0, 1);
        sum0 += __shfl_xor_sync(0xffffffffu, sum0, 2);
        sum1 += __shfl_xor_sync(0xffffffffu, sum1, 1);
        sum1 += __shfl_xor_sync(0xffffffffu, sum1, 2);
        l0 = l0 * c0f + sum0;
        l1 = l1 * c1f + sum1;
        m0 = mn0; m1 = mn1;

        // ---- O += P . V  (P already in A-fragment layout) ----
        #pragma unroll
        for (int j = 0; j < 4; ++j) {
            unsigned ah[4] = {ph[2*j][0], ph[2*j][1], ph[2*j+1][0], ph[2*j+1][1]};
            unsigned al[4] = {pl[2*j][0], pl[2*j][1], pl[2*j+1][0], pl[2*j+1][1]};
            #pragma unroll
            for (int sub = 0; sub < 8; ++sub) {
                const int br = (sub * 8 + g) * TSTRIDE + j * 8;
                unsigned bh0 = Vh[br + tig], bh1 = Vh[br + tig + 4];
                unsigned bl0 = Vl[br + tig], bl1 = Vl[br + tig + 4];
                mma_bf16(o[sub], ah, bh0, bh1);
                mma_bf16(o[sub], ah, bl0, bl1);
                mma_bf16(o[sub], al, bh0, bh1);
            }
        }

        __syncthreads();   // all warps done reading buf[kt&1] before it's refilled
    }

    // ---- epilogue ----
    const float inv0 = 1.f / l0;
    const float inv1 = 1.f / l1;
    float* base0 = out + ((size_t)(b * LL + q0 + g0 + g)) * AA;
    float* base1 = base0 + (size_t)8 * AA;
    #pragma unroll
    for (int sub = 0; sub < 8; ++sub) {
        const int dcol = sub * 8 + 2 * tig;
        *(float2*)&base0[dcol] = make_float2(o[sub][0] * inv0, o[sub][1] * inv0);
        *(float2*)&base1[dcol] = make_float2(o[sub][2] * inv1, o[sub][3] * inv1);
    }
}

// ---------------------------------------------------------------------------
extern "C" void kernel_launch(void* const* d_in, const int* in_sizes, int n_in,
                              void* d_out, int out_size) {
    (void)in_sizes; (void)n_in; (void)out_size;
    const float* x  = (const float*)d_in[0];
    const float* Wq = (const float*)d_in[1];
    const float* Wk = (const float*)d_in[2];
    const float* Wv = (const float*)d_in[3];
    float* out = (float*)d_out;

    {
        dim3 grid(NROWS / 64, 3);
        qkv_kernel<<<grid, 256>>>(x, Wq, Wk, Wv);
    }
    {
        size_t smem = (size_t)2 * 4 * TILE_U32 * sizeof(unsigned);  // 73728 B
        cudaFuncSetAttribute(attn_kernel, cudaFuncAttributeMaxDynamicSharedMemorySize, (int)smem);
        attn_kernel<<<256, 128, smem>>>(out);
    }
}

// round 5
// speedup vs baseline: 2.5476x; 1.0281x over previous
#include <cuda_runtime.h>
#include <cuda_bf16.h>
#include <math.h>

#define BB 4
#define LL 4096
#define DD 256
#define AA 64
#define NROWS (BB*LL)
#define NPAIR 32           // 64 elems -> 32 bf16x2 pairs
#define DPAIR 128          // 256 dims -> 128 pairs
#define TSTRIDE 36         // attn smem tile row stride (u32)
#define XSTRIDE 132        // qkv  smem x-tile row stride (u32)
#define NCH 4              // max chunks per query tile
#define CHT 16             // tiles per chunk

// Packed bf16 hi/lo splits
__device__ unsigned g_qhi[NROWS*NPAIR], g_qlo[NROWS*NPAIR];
__device__ unsigned g_khi[NROWS*NPAIR], g_klo[NROWS*NPAIR];
__device__ unsigned g_vthi[BB*AA*(LL/2)], g_vtlo[BB*AA*(LL/2)];  // [b][d][keypair]
// Packed inputs for tensor-core QKV
__device__ unsigned g_xp_hi[NROWS*DPAIR], g_xp_lo[NROWS*DPAIR];   // [row][dpair]
__device__ unsigned g_wtp_hi[3*AA*DPAIR], g_wtp_lo[3*AA*DPAIR];   // [mat][a][dpair]
// Split-KV partials
__device__ float g_pO[BB*64*NCH*64*64];   // [(b*64+qt)*4+ch][row][col]
__device__ float g_pm[BB*64*NCH*64];
__device__ float g_pl[BB*64*NCH*64];

// ---------------------------------------------------------------------------
__device__ __forceinline__ void split2(float f0, float f1, unsigned &hi, unsigned &lo) {
    unsigned short h0 = __bfloat16_as_ushort(__float2bfloat16_rn(f0));
    unsigned short h1 = __bfloat16_as_ushort(__float2bfloat16_rn(f1));
    float r0 = f0 - __bfloat162float(__ushort_as_bfloat16(h0));
    float r1 = f1 - __bfloat162float(__ushort_as_bfloat16(h1));
    unsigned short e0 = __bfloat16_as_ushort(__float2bfloat16_rn(r0));
    unsigned short e1 = __bfloat16_as_ushort(__float2bfloat16_rn(r1));
    hi = (unsigned)h0 | ((unsigned)h1 << 16);
    lo = (unsigned)e0 | ((unsigned)e1 << 16);
}

__device__ __forceinline__ void mma_bf16(float (&d)[4], const unsigned (&a)[4],
                                         unsigned b0, unsigned b1) {
    asm volatile(
        "mma.sync.aligned.m16n8k16.row.col.f32.bf16.bf16.f32 "
        "{%0,%1,%2,%3}, {%4,%5,%6,%7}, {%8,%9}, {%0,%1,%2,%3};"
        : "+f"(d[0]), "+f"(d[1]), "+f"(d[2]), "+f"(d[3])
        : "r"(a[0]), "r"(a[1]), "r"(a[2]), "r"(a[3]), "r"(b0), "r"(b1));
}

__device__ __forceinline__ void cpa16(void* s, const void* g) {
    unsigned sa = (unsigned)__cvta_generic_to_shared(s);
    asm volatile("cp.async.cg.shared.global [%0], [%1], 16;" :: "r"(sa), "l"(g));
}

// ---------------------------------------------------------------------------
// Kernel 0: prep — split x and W into packed bf16 hi/lo.
// ---------------------------------------------------------------------------
__global__ void prep_kernel(const float* __restrict__ x,
                            const float* __restrict__ Wq,
                            const float* __restrict__ Wk,
                            const float* __restrict__ Wv) {
    const int total_x = NROWS * DPAIR;
    for (int i = blockIdx.x * blockDim.x + threadIdx.x; i < total_x;
         i += gridDim.x * blockDim.x) {
        float2 f = ((const float2*)x)[i];
        split2(f.x, f.y, g_xp_hi[i], g_xp_lo[i]);
    }
    // W: 3 * 64 * 128 pairs
    const int total_w = 3 * AA * DPAIR;
    for (int i = blockIdx.x * blockDim.x + threadIdx.x; i < total_w;
         i += gridDim.x * blockDim.x) {
        int m = i / (AA * DPAIR);
        int r = i % (AA * DPAIR);
        int a = r >> 7, p = r & 127;
        const float* W = (m == 0) ? Wq : (m == 1) ? Wk : Wv;
        float w0 = W[(size_t)(2*p)   * AA + a];
        float w1 = W[(size_t)(2*p+1) * AA + a];
        split2(w0, w1, g_wtp_hi[i], g_wtp_lo[i]);
    }
}

// ---------------------------------------------------------------------------
// Kernel 1: QKV projection on tensor cores (3-term bf16 split, exact-ish).
// grid = (NROWS/64, 3), block = 128 (4 warps x 16 rows).
// ---------------------------------------------------------------------------
__global__ __launch_bounds__(128)
void qkv_kernel() {
    extern __shared__ unsigned qsm[];
    unsigned* xs_hi = qsm;                 // [64][XSTRIDE]
    unsigned* xs_lo = qsm + 64 * XSTRIDE;

    const int row0 = blockIdx.x * 64;
    const int mat  = blockIdx.y;
    const int tid  = threadIdx.x;
    const int wid  = tid >> 5;
    const int lane = tid & 31;
    const int g    = lane >> 2;
    const int tig  = lane & 3;
    const int g0   = wid * 16;

    // Stage x tile (64 rows x 128 pairs, hi+lo) into smem
    {
        int r = tid >> 1;             // 0..63
        int h = (tid & 1) * 64;       // half-row offset in u32
        const uint4* sh = (const uint4*)&g_xp_hi[(size_t)(row0 + r) * DPAIR + h];
        const uint4* sl = (const uint4*)&g_xp_lo[(size_t)(row0 + r) * DPAIR + h];
        uint4* dh = (uint4*)&xs_hi[r * XSTRIDE + h];
        uint4* dl = (uint4*)&xs_lo[r * XSTRIDE + h];
        #pragma unroll
        for (int i = 0; i < 16; ++i) { dh[i] = sh[i]; dl[i] = sl[i]; }
    }
    __syncthreads();

    float o[8][4] = {};
    const unsigned* wph = g_wtp_hi + (size_t)mat * AA * DPAIR;
    const unsigned* wpl = g_wtp_lo + (size_t)mat * AA * DPAIR;

    #pragma unroll 4
    for (int ks = 0; ks < 16; ++ks) {       // 16 k16-chunks over 256 dims
        unsigned ah[4], al[4];
        const int ar0 = (g0 + g) * XSTRIDE + ks * 8;
        const int ar1 = ar0 + 8 * XSTRIDE;
        ah[0] = xs_hi[ar0 + tig];     ah[1] = xs_hi[ar1 + tig];
        ah[2] = xs_hi[ar0 + tig + 4]; ah[3] = xs_hi[ar1 + tig + 4];
        al[0] = xs_lo[ar0 + tig];     al[1] = xs_lo[ar1 + tig];
        al[2] = xs_lo[ar0 + tig + 4]; al[3] = xs_lo[ar1 + tig + 4];
        #pragma unroll
        for (int sub = 0; sub < 8; ++sub) {
            const int br = (sub * 8 + g) * DPAIR + ks * 8;
            unsigned bh0 = wph[br + tig], bh1 = wph[br + tig + 4];
            unsigned bl0 = wpl[br + tig], bl1 = wpl[br + tig + 4];
            mma_bf16(o[sub], ah, bh0, bh1);
            mma_bf16(o[sub], ah, bl0, bl1);
            mma_bf16(o[sub], al, bh0, bh1);
        }
    }

    if (mat < 2) {
        unsigned* dh = (mat == 0) ? g_qhi : g_khi;
        unsigned* dl = (mat == 0) ? g_qlo : g_klo;
        const int ra = row0 + g0 + g;
        #pragma unroll
        for (int sub = 0; sub < 8; ++sub) {
            unsigned h, l;
            split2(o[sub][0], o[sub][1], h, l);
            dh[(size_t)ra * NPAIR + sub*4 + tig] = h;
            dl[(size_t)ra * NPAIR + sub*4 + tig] = l;
            split2(o[sub][2], o[sub][3], h, l);
            dh[(size_t)(ra+8) * NPAIR + sub*4 + tig] = h;
            dl[(size_t)(ra+8) * NPAIR + sub*4 + tig] = l;
        }
    } else {
        // V: transpose via smem (reuse buffer), emit [b][d][keypair]
        __syncthreads();
        float* smf = (float*)qsm;          // [64][68]
        const int rr = g0 + g;
        #pragma unroll
        for (int sub = 0; sub < 8; ++sub) {
            const int dc = sub * 8 + 2 * tig;
            smf[rr * 68 + dc]       = o[sub][0];
            smf[rr * 68 + dc + 1]   = o[sub][1];
            smf[(rr+8) * 68 + dc]   = o[sub][2];
            smf[(rr+8) * 68 + dc+1] = o[sub][3];
        }
        __syncthreads();
        const int b  = row0 / LL;
        const int lr = row0 % LL;
        const int d    = tid & 63;
        const int half = tid >> 6;
        #pragma unroll
        for (int i = 0; i < 16; ++i) {
            int kp = half * 16 + i;
            float v0 = smf[(2*kp)   * 68 + d];
            float v1 = smf[(2*kp+1) * 68 + d];
            unsigned h, l;
            split2(v0, v1, h, l);
            size_t idx = (size_t)(b * AA + d) * (LL/2) + (lr >> 1) + kp;
            g_vthi[idx] = h; g_vtlo[idx] = l;
        }
    }
}

// ---------------------------------------------------------------------------
// Kernel 2: causal flash attention, split-KV chunks of 16 tiles.
// grid = 640 (LPT job order), block = 128.  Writes unnormalized partials.
// ---------------------------------------------------------------------------
#define TILE_U32 (64 * TSTRIDE)

__global__ __launch_bounds__(128)
void attn_kernel() {
    extern __shared__ unsigned smbuf[];
    const int gx  = blockIdx.x;
    const int b   = gx & 3;
    const int jj  = gx >> 2;             // 0..159, longest chunks first
    int qt, chunk;
    if (jj < 64)       { qt = 48 + (jj >> 2);        chunk = jj & 3; }
    else if (jj < 112) { int t = jj - 64;  qt = 32 + t / 3;    chunk = t % 3; }
    else if (jj < 144) { int t = jj - 112; qt = 16 + (t >> 1); chunk = t & 1; }
    else               { qt = jj - 144;              chunk = 0; }

    const int q0  = qt * 64;
    const int kt0 = chunk * CHT;
    const int nt  = min(CHT, qt + 1 - kt0);  // tiles in this chunk (>=1)

    const int tid = threadIdx.x;
    const int wid = tid >> 5;
    const int lane = tid & 31;
    const int g   = lane >> 2;
    const int tig = lane & 3;
    const int g0  = wid * 16;

    const int crow = tid >> 1;
    const int ccol = (tid & 1) * 16;

    // ---- Q fragments (loop-invariant) ----
    unsigned qh[4][4], ql[4][4];
    {
        const unsigned* qbh = g_qhi + (size_t)(b*LL + q0) * NPAIR;
        const unsigned* qbl = g_qlo + (size_t)(b*LL + q0) * NPAIR;
        const int ra = (g0 + g) * NPAIR;
        const int rb = ra + 8 * NPAIR;
        #pragma unroll
        for (int ks = 0; ks < 4; ++ks) {
            const int p0 = ks * 8 + tig;
            qh[ks][0] = qbh[ra + p0];     qh[ks][1] = qbh[rb + p0];
            qh[ks][2] = qbh[ra + p0 + 4]; qh[ks][3] = qbh[rb + p0 + 4];
            ql[ks][0] = qbl[ra + p0];     ql[ks][1] = qbl[rb + p0];
            ql[ks][2] = qbl[ra + p0 + 4]; ql[ks][3] = qbl[rb + p0 + 4];
        }
    }

    auto prefetch = [&](int bufsel, int k0) {
        unsigned* base = smbuf + bufsel * 4 * TILE_U32;
        unsigned* dkh = base              + crow * TSTRIDE + ccol;
        unsigned* dkl = base + 1*TILE_U32 + crow * TSTRIDE + ccol;
        unsigned* dvh = base + 2*TILE_U32 + crow * TSTRIDE + ccol;
        unsigned* dvl = base + 3*TILE_U32 + crow * TSTRIDE + ccol;
        const unsigned* skh = &g_khi [(size_t)(b*LL + k0 + crow) * NPAIR + ccol];
        const unsigned* skl = &g_klo [(size_t)(b*LL + k0 + crow) * NPAIR + ccol];
        const unsigned* svh = &g_vthi[(size_t)(b*AA + crow) * (LL/2) + (k0 >> 1) + ccol];
        const unsigned* svl = &g_vtlo[(size_t)(b*AA + crow) * (LL/2) + (k0 >> 1) + ccol];
        #pragma unroll
        for (int i = 0; i < 4; ++i) {
            cpa16(dkh + 4*i, skh + 4*i);
            cpa16(dkl + 4*i, skl + 4*i);
            cpa16(dvh + 4*i, svh + 4*i);
            cpa16(dvl + 4*i, svl + 4*i);
        }
        asm volatile("cp.async.commit_group;");
    };

    prefetch(0, kt0 * 64);

    float o[8][4] = {};
    float m0 = -INFINITY, m1 = -INFINITY, l0 = 0.f, l1 = 0.f;

    for (int t = 0; t < nt; ++t) {
        const int kt = kt0 + t;
        if (t < nt - 1) {
            prefetch((t + 1) & 1, (kt + 1) * 64);
            asm volatile("cp.async.wait_group 1;");
        } else {
            asm volatile("cp.async.wait_group 0;");
        }
        __syncthreads();

        const unsigned* base = smbuf + (t & 1) * 4 * TILE_U32;
        const unsigned* Kh = base;
        const unsigned* Kl = base + 1*TILE_U32;
        const unsigned* Vh = base + 2*TILE_U32;
        const unsigned* Vl = base + 3*TILE_U32;

        float s[8][4];
        #pragma unroll
        for (int sub = 0; sub < 8; ++sub)
            #pragma unroll
            for (int i = 0; i < 4; ++i) s[sub][i] = 0.f;

        #pragma unroll
        for (int ks = 0; ks < 4; ++ks) {
            #pragma unroll
            for (int sub = 0; sub < 8; ++sub) {
                const int br = (sub * 8 + g) * TSTRIDE + ks * 8;
                unsigned bh0 = Kh[br + tig], bh1 = Kh[br + tig + 4];
                unsigned bl0 = Kl[br + tig], bl1 = Kl[br + tig + 4];
                mma_bf16(s[sub], qh[ks], bh0, bh1);
                mma_bf16(s[sub], qh[ks], bl0, bl1);
                mma_bf16(s[sub], ql[ks], bh0, bh1);
            }
        }

        if (kt == qt) {
            #pragma unroll
            for (int sub = 0; sub < 8; ++sub) {
                const int kc = sub * 8 + 2 * tig;
                const int r_lo = g0 + g, r_hi = r_lo + 8;
                if (kc     > r_lo) s[sub][0] = -INFINITY;
                if (kc + 1 > r_lo) s[sub][1] = -INFINITY;
                if (kc     > r_hi) s[sub][2] = -INFINITY;
                if (kc + 1 > r_hi) s[sub][3] = -INFINITY;
            }
        }

        float mt0 = -INFINITY, mt1 = -INFINITY;
        #pragma unroll
        for (int sub = 0; sub < 8; ++sub) {
            mt0 = fmaxf(mt0, fmaxf(s[sub][0], s[sub][1]));
            mt1 = fmaxf(mt1, fmaxf(s[sub][2], s[sub][3]));
        }
        mt0 = fmaxf(mt0, __shfl_xor_sync(0xffffffffu, mt0, 1));
        mt0 = fmaxf(mt0, __shfl_xor_sync(0xffffffffu, mt0, 2));
        mt1 = fmaxf(mt1, __shfl_xor_sync(0xffffffffu, mt1, 1));
        mt1 = fmaxf(mt1, __shfl_xor_sync(0xffffffffu, mt1, 2));

        const float mn0 = fmaxf(m0, mt0);
        const float mn1 = fmaxf(m1, mt1);
        const float c0f = __expf(m0 - mn0);
        const float c1f = __expf(m1 - mn1);

        unsigned ph[8][2], pl[8][2];
        float sum0 = 0.f, sum1 = 0.f;
        #pragma unroll
        for (int sub = 0; sub < 8; ++sub) {
            float p0 = __expf(s[sub][0] - mn0);
            float p1 = __expf(s[sub][1] - mn0);
            float p2 = __expf(s[sub][2] - mn1);
            float p3 = __expf(s[sub][3] - mn1);
            sum0 += p0 + p1;  sum1 += p2 + p3;
            split2(p0, p1, ph[sub][0], pl[sub][0]);
            split2(p2, p3, ph[sub][1], pl[sub][1]);
            o[sub][0] *= c0f; o[sub][1] *= c0f;
            o[sub][2] *= c1f; o[sub][3] *= c1f;
        }
        sum0 += __shfl_xor_sync(0xffffffffu, sum0, 1);
        sum0 += __shfl_xor_sync(0xffffffffu, sum0, 2);
        sum1 += __shfl_xor_sync(0xffffffffu, sum1, 1);
        sum1 += __shfl_xor_sync(0xffffffffu, sum1, 2);
        l0 = l0 * c0f + sum0;
        l1 = l1 * c1f + sum1;
        m0 = mn0; m1 = mn1;

        #pragma unroll
        for (int j = 0; j < 4; ++j) {
            unsigned ah[4] = {ph[2*j][0], ph[2*j][1], ph[2*j+1][0], ph[2*j+1][1]};
            unsigned al[4] = {pl[2*j][0], pl[2*j][1], pl[2*j+1][0], pl[2*j+1][1]};
            #pragma unroll
            for (int sub = 0; sub < 8; ++sub) {
                const int br = (sub * 8 + g) * TSTRIDE + j * 8;
                unsigned bh0 = Vh[br + tig], bh1 = Vh[br + tig + 4];
                unsigned bl0 = Vl[br + tig], bl1 = Vl[br + tig + 4];
                mma_bf16(o[sub], ah, bh0, bh1);
                mma_bf16(o[sub], ah, bl0, bl1);
                mma_bf16(o[sub], al, bh0, bh1);
            }
        }

        __syncthreads();
    }

    // ---- write unnormalized partials ----
    const int slot = ((b * 64 + qt) * NCH + chunk);
    float* po = g_pO + (size_t)slot * 4096;
    #pragma unroll
    for (int sub = 0; sub < 8; ++sub) {
        const int dcol = sub * 8 + 2 * tig;
        *(float2*)&po[(g0 + g) * 64 + dcol]     = make_float2(o[sub][0], o[sub][1]);
        *(float2*)&po[(g0 + g + 8) * 64 + dcol] = make_float2(o[sub][2], o[sub][3]);
    }
    if (tig == 0) {
        g_pm[slot * 64 + g0 + g]     = m0;
        g_pm[slot * 64 + g0 + g + 8] = m1;
        g_pl[slot * 64 + g0 + g]     = l0;
        g_pl[slot * 64 + g0 + g + 8] = l1;
    }
}

// ---------------------------------------------------------------------------
// Kernel 3: merge split-KV partials.  grid = 256 (b*64+qt), block = 256.
// ---------------------------------------------------------------------------
__global__ __launch_bounds__(256)
void merge_kernel(float* __restrict__ out) {
    const int bq  = blockIdx.x;
    const int b   = bq >> 6;
    const int qt  = bq & 63;
    const int nch = qt / CHT + 1;
    const int base_slot = bq * NCH;

    for (int e = threadIdx.x; e < 4096; e += 256) {
        const int row = e >> 6;
        const int col = e & 63;
        float M = -INFINITY;
        #pragma unroll
        for (int c = 0; c < NCH; ++c)
            if (c < nch) M = fmaxf(M, g_pm[(base_slot + c) * 64 + row]);
        float denom = 0.f, acc = 0.f;
        #pragma unroll
        for (int c = 0; c < NCH; ++c) {
            if (c < nch) {
                float w = __expf(g_pm[(base_slot + c) * 64 + row] - M);
                denom += w * g_pl[(base_slot + c) * 64 + row];
                acc   += w * g_pO[(size_t)(base_slot + c) * 4096 + e];
            }
        }
        out[((size_t)(b * LL + qt * 64 + row)) * 64 + col] = acc / denom;
    }
}

// ---------------------------------------------------------------------------
extern "C" void kernel_launch(void* const* d_in, const int* in_sizes, int n_in,
                              void* d_out, int out_size) {
    (void)in_sizes; (void)n_in; (void)out_size;
    const float* x  = (const float*)d_in[0];
    const float* Wq = (const float*)d_in[1];
    const float* Wk = (const float*)d_in[2];
    const float* Wv = (const float*)d_in[3];
    float* out = (float*)d_out;

    prep_kernel<<<512, 256>>>(x, Wq, Wk, Wv);

    {
        size_t smem = (size_t)2 * 64 * XSTRIDE * sizeof(unsigned);  // 67584 B
        cudaFuncSetAttribute(qkv_kernel, cudaFuncAttributeMaxDynamicSharedMemorySize, (int)smem);
        dim3 grid(NROWS / 64, 3);
        qkv_kernel<<<grid, 128, smem>>>();
    }
    {
        size_t smem = (size_t)2 * 4 * TILE_U32 * sizeof(unsigned);  // 73728 B
        cudaFuncSetAttribute(attn_kernel, cudaFuncAttributeMaxDynamicSharedMemorySize, (int)smem);
        attn_kernel<<<640, 128, smem>>>();
    }
    merge_kernel<<<256, 256>>>(out);
}

// round 6
// speedup vs baseline: 3.9764x; 1.5609x over previous
#include <cuda_runtime.h>
#include <cuda_bf16.h>
#include <math.h>

#define BB 4
#define LL 4096
#define DD 256
#define AA 64
#define NROWS (BB*LL)
#define NPAIR 32           // 64 elems -> 32 bf16x2 pairs
#define DPAIR 128          // 256 dims -> 128 pairs
#define TSTRIDE 36         // smem tile row stride (u32), conflict-free frags
#define NCH 4              // max chunks per 128-row query tile
#define CHT 16             // key-tiles per chunk
#define NQT 32             // 128-row query tiles per batch

// Packed bf16 hi/lo splits
__device__ unsigned g_qhi[NROWS*NPAIR], g_qlo[NROWS*NPAIR];
__device__ unsigned g_khi[NROWS*NPAIR], g_klo[NROWS*NPAIR];
__device__ unsigned g_vthi[BB*AA*(LL/2)], g_vtlo[BB*AA*(LL/2)];  // [b][d][keypair]
__device__ unsigned g_wtp_hi[3*AA*DPAIR], g_wtp_lo[3*AA*DPAIR];  // [mat][a][dpair]
// Split-KV partials: slot = (b*NQT+qt2)*NCH+chunk, 128 rows x 64 cols
__device__ float g_pO[BB*NQT*NCH*128*64];
__device__ float g_pm[BB*NQT*NCH*128];
__device__ float g_pl[BB*NQT*NCH*128];

// ---------------------------------------------------------------------------
__device__ __forceinline__ void split2(float f0, float f1, unsigned &hi, unsigned &lo) {
    unsigned short h0 = __bfloat16_as_ushort(__float2bfloat16_rn(f0));
    unsigned short h1 = __bfloat16_as_ushort(__float2bfloat16_rn(f1));
    float r0 = f0 - __bfloat162float(__ushort_as_bfloat16(h0));
    float r1 = f1 - __bfloat162float(__ushort_as_bfloat16(h1));
    unsigned short e0 = __bfloat16_as_ushort(__float2bfloat16_rn(r0));
    unsigned short e1 = __bfloat16_as_ushort(__float2bfloat16_rn(r1));
    hi = (unsigned)h0 | ((unsigned)h1 << 16);
    lo = (unsigned)e0 | ((unsigned)e1 << 16);
}

__device__ __forceinline__ void mma_bf16(float (&d)[4], const unsigned (&a)[4],
                                         unsigned b0, unsigned b1) {
    asm volatile(
        "mma.sync.aligned.m16n8k16.row.col.f32.bf16.bf16.f32 "
        "{%0,%1,%2,%3}, {%4,%5,%6,%7}, {%8,%9}, {%0,%1,%2,%3};"
        : "+f"(d[0]), "+f"(d[1]), "+f"(d[2]), "+f"(d[3])
        : "r"(a[0]), "r"(a[1]), "r"(a[2]), "r"(a[3]), "r"(b0), "r"(b1));
}

__device__ __forceinline__ void cpa16(void* s, const void* g) {
    unsigned sa = (unsigned)__cvta_generic_to_shared(s);
    asm volatile("cp.async.cg.shared.global [%0], [%1], 16;" :: "r"(sa), "l"(g));
}

// ---------------------------------------------------------------------------
// Kernel 0: split W into packed [mat][a][dpair] hi/lo (tiny).
// ---------------------------------------------------------------------------
__global__ void prepw_kernel(const float* __restrict__ Wq,
                             const float* __restrict__ Wk,
                             const float* __restrict__ Wv) {
    const int total = 3 * AA * DPAIR;
    for (int i = blockIdx.x * blockDim.x + threadIdx.x; i < total;
         i += gridDim.x * blockDim.x) {
        int m = i / (AA * DPAIR);
        int r = i % (AA * DPAIR);
        int a = r >> 7, p = r & 127;
        const float* W = (m == 0) ? Wq : (m == 1) ? Wk : Wv;
        float w0 = W[(size_t)(2*p)   * AA + a];
        float w1 = W[(size_t)(2*p+1) * AA + a];
        split2(w0, w1, g_wtp_hi[i], g_wtp_lo[i]);
    }
}

// ---------------------------------------------------------------------------
// Kernel 1: QKV projection on tensor cores; x split on the fly, W from
// pre-split packed gmem, both staged in smem per 64-dim chunk.
// grid = (3, NROWS/64), block = 128.
// ---------------------------------------------------------------------------
__global__ __launch_bounds__(128)
void qkv_kernel(const float* __restrict__ x) {
    __shared__ unsigned xs_hi[64*TSTRIDE], xs_lo[64*TSTRIDE];
    __shared__ unsigned ws_hi[64*TSTRIDE], ws_lo[64*TSTRIDE];

    const int mat  = blockIdx.x;
    const int row0 = blockIdx.y * 64;
    const int tid  = threadIdx.x;
    const int wid  = tid >> 5;
    const int lane = tid & 31;
    const int g    = lane >> 2;
    const int tig  = lane & 3;
    const int g0   = wid * 16;

    float o[8][4] = {};

    for (int d0 = 0; d0 < DD; d0 += 64) {
        __syncthreads();
        // stage x chunk: 64 rows x 32 pairs, split on the fly
        {
            const int r = tid >> 1;
            const int p0 = (tid & 1) * 16;           // pair offset
            const float* src = x + (size_t)(row0 + r) * DD + d0 + p0 * 2;
            unsigned* dh = &xs_hi[r * TSTRIDE + p0];
            unsigned* dl = &xs_lo[r * TSTRIDE + p0];
            #pragma unroll
            for (int i = 0; i < 8; ++i) {
                float4 f = *(const float4*)(src + 4*i);
                split2(f.x, f.y, dh[2*i],   dl[2*i]);
                split2(f.z, f.w, dh[2*i+1], dl[2*i+1]);
            }
        }
        // stage W chunk: 64 a-rows x 32 pairs (pre-packed)
        {
            const int a  = tid >> 1;
            const int p0 = (tid & 1) * 16;
            const uint4* sh = (const uint4*)&g_wtp_hi[(size_t)mat*AA*DPAIR + a*DPAIR + (d0>>1) + p0];
            const uint4* sl = (const uint4*)&g_wtp_lo[(size_t)mat*AA*DPAIR + a*DPAIR + (d0>>1) + p0];
            uint4* dh = (uint4*)&ws_hi[a * TSTRIDE + p0];
            uint4* dl = (uint4*)&ws_lo[a * TSTRIDE + p0];
            #pragma unroll
            for (int i = 0; i < 4; ++i) { dh[i] = sh[i]; dl[i] = sl[i]; }
        }
        __syncthreads();

        #pragma unroll
        for (int ks = 0; ks < 4; ++ks) {
            unsigned ah[4], al[4];
            const int ar0 = (g0 + g) * TSTRIDE + ks * 8;
            const int ar1 = ar0 + 8 * TSTRIDE;
            ah[0] = xs_hi[ar0 + tig];     ah[1] = xs_hi[ar1 + tig];
            ah[2] = xs_hi[ar0 + tig + 4]; ah[3] = xs_hi[ar1 + tig + 4];
            al[0] = xs_lo[ar0 + tig];     al[1] = xs_lo[ar1 + tig];
            al[2] = xs_lo[ar0 + tig + 4]; al[3] = xs_lo[ar1 + tig + 4];
            #pragma unroll
            for (int sub = 0; sub < 8; ++sub) {
                const int br = (sub * 8 + g) * TSTRIDE + ks * 8;
                unsigned bh0 = ws_hi[br + tig], bh1 = ws_hi[br + tig + 4];
                unsigned bl0 = ws_lo[br + tig], bl1 = ws_lo[br + tig + 4];
                mma_bf16(o[sub], ah, bh0, bh1);
                mma_bf16(o[sub], ah, bl0, bl1);
                mma_bf16(o[sub], al, bh0, bh1);
            }
        }
    }

    if (mat < 2) {
        unsigned* dh = (mat == 0) ? g_qhi : g_khi;
        unsigned* dl = (mat == 0) ? g_qlo : g_klo;
        const int ra = row0 + g0 + g;
        #pragma unroll
        for (int sub = 0; sub < 8; ++sub) {
            unsigned h, l;
            split2(o[sub][0], o[sub][1], h, l);
            dh[(size_t)ra * NPAIR + sub*4 + tig] = h;
            dl[(size_t)ra * NPAIR + sub*4 + tig] = l;
            split2(o[sub][2], o[sub][3], h, l);
            dh[(size_t)(ra+8) * NPAIR + sub*4 + tig] = h;
            dl[(size_t)(ra+8) * NPAIR + sub*4 + tig] = l;
        }
    } else {
        // V: transpose via smem, emit [b][d][keypair]
        __syncthreads();
        float* smf = (float*)xs_hi;          // reuse: [64][68] floats
        const int rr = g0 + g;
        #pragma unroll
        for (int sub = 0; sub < 8; ++sub) {
            const int dc = sub * 8 + 2 * tig;
            smf[rr * 68 + dc]       = o[sub][0];
            smf[rr * 68 + dc + 1]   = o[sub][1];
            smf[(rr+8) * 68 + dc]   = o[sub][2];
            smf[(rr+8) * 68 + dc+1] = o[sub][3];
        }
        __syncthreads();
        const int b  = row0 / LL;
        const int lr = row0 % LL;
        const int d    = tid & 63;
        const int half = tid >> 6;
        #pragma unroll
        for (int i = 0; i < 16; ++i) {
            int kp = half * 16 + i;
            float v0 = smf[(2*kp)   * 68 + d];
            float v1 = smf[(2*kp+1) * 68 + d];
            unsigned h, l;
            split2(v0, v1, h, l);
            size_t idx = (size_t)(b * AA + d) * (LL/2) + (lr >> 1) + kp;
            g_vthi[idx] = h; g_vtlo[idx] = l;
        }
    }
}

// ---------------------------------------------------------------------------
// Kernel 2: causal flash attention, BM=128 (8 warps), split-KV chunks of 16
// key-tiles.  grid = 320 (LPT), block = 256.  Unnormalized partials out.
// ---------------------------------------------------------------------------
#define TILE_U32 (64 * TSTRIDE)

__global__ __launch_bounds__(256, 2)
void attn_kernel() {
    extern __shared__ unsigned smbuf[];
    const int gx = blockIdx.x;
    const int b  = gx & 3;
    const int jj = gx >> 2;              // 0..79, longest chunks first
    int qt2, chunk;
    if (jj < 32)      { qt2 = 24 + (jj >> 2);        chunk = jj & 3; }
    else if (jj < 56) { int t = jj - 32; qt2 = 16 + t / 3;    chunk = t % 3; }
    else if (jj < 72) { int t = jj - 56; qt2 = 8 + (t >> 1);  chunk = t & 1; }
    else              { qt2 = jj - 72;               chunk = 0; }

    const int q0    = qt2 * 128;
    const int tiles = 2 * qt2 + 2;
    const int kt0   = chunk * CHT;
    const int nt    = min(CHT, tiles - kt0);

    const int tid = threadIdx.x;
    const int wid = tid >> 5;
    const int lane = tid & 31;
    const int g   = lane >> 2;
    const int tig = lane & 3;
    const int g0  = wid * 16;

    // copy mapping: 256 threads, per array 64 rows x 32 u32 -> 2 cpa16/thread
    const int crow = tid >> 2;
    const int ccol = (tid & 3) * 8;

    // ---- Q fragments (loop-invariant) ----
    unsigned qh[4][4], ql[4][4];
    {
        const unsigned* qbh = g_qhi + (size_t)(b*LL + q0) * NPAIR;
        const unsigned* qbl = g_qlo + (size_t)(b*LL + q0) * NPAIR;
        const int ra = (g0 + g) * NPAIR;
        const int rb = ra + 8 * NPAIR;
        #pragma unroll
        for (int ks = 0; ks < 4; ++ks) {
            const int p0 = ks * 8 + tig;
            qh[ks][0] = qbh[ra + p0];     qh[ks][1] = qbh[rb + p0];
            qh[ks][2] = qbh[ra + p0 + 4]; qh[ks][3] = qbh[rb + p0 + 4];
            ql[ks][0] = qbl[ra + p0];     ql[ks][1] = qbl[rb + p0];
            ql[ks][2] = qbl[ra + p0 + 4]; ql[ks][3] = qbl[rb + p0 + 4];
        }
    }

    auto prefetch = [&](int bufsel, int k0) {
        unsigned* base = smbuf + bufsel * 4 * TILE_U32;
        unsigned* dkh = base              + crow * TSTRIDE + ccol;
        unsigned* dkl = base + 1*TILE_U32 + crow * TSTRIDE + ccol;
        unsigned* dvh = base + 2*TILE_U32 + crow * TSTRIDE + ccol;
        unsigned* dvl = base + 3*TILE_U32 + crow * TSTRIDE + ccol;
        const unsigned* skh = &g_khi [(size_t)(b*LL + k0 + crow) * NPAIR + ccol];
        const unsigned* skl = &g_klo [(size_t)(b*LL + k0 + crow) * NPAIR + ccol];
        const unsigned* svh = &g_vthi[(size_t)(b*AA + crow) * (LL/2) + (k0 >> 1) + ccol];
        const unsigned* svl = &g_vtlo[(size_t)(b*AA + crow) * (LL/2) + (k0 >> 1) + ccol];
        cpa16(dkh, skh); cpa16(dkh + 4, skh + 4);
        cpa16(dkl, skl); cpa16(dkl + 4, skl + 4);
        cpa16(dvh, svh); cpa16(dvh + 4, svh + 4);
        cpa16(dvl, svl); cpa16(dvl + 4, svl + 4);
        asm volatile("cp.async.commit_group;");
    };

    prefetch(0, kt0 * 64);

    float o[8][4] = {};
    float m0 = -INFINITY, m1 = -INFINITY, l0 = 0.f, l1 = 0.f;

    for (int t = 0; t < nt; ++t) {
        const int kt = kt0 + t;
        if (t < nt - 1) {
            prefetch((t + 1) & 1, (kt + 1) * 64);
            asm volatile("cp.async.wait_group 1;");
        } else {
            asm volatile("cp.async.wait_group 0;");
        }
        __syncthreads();

        // warps below the diagonal skip the fully-masked diag+1 tile
        const bool active = !(kt == 2*qt2 + 1 && g0 < 64);
        if (active) {
            const unsigned* base = smbuf + (t & 1) * 4 * TILE_U32;
            const unsigned* Kh = base;
            const unsigned* Kl = base + 1*TILE_U32;
            const unsigned* Vh = base + 2*TILE_U32;
            const unsigned* Vl = base + 3*TILE_U32;

            float s[8][4];
            #pragma unroll
            for (int sub = 0; sub < 8; ++sub)
                #pragma unroll
                for (int i = 0; i < 4; ++i) s[sub][i] = 0.f;

            #pragma unroll
            for (int ks = 0; ks < 4; ++ks) {
                #pragma unroll
                for (int sub = 0; sub < 8; ++sub) {
                    const int br = (sub * 8 + g) * TSTRIDE + ks * 8;
                    unsigned bh0 = Kh[br + tig], bh1 = Kh[br + tig + 4];
                    unsigned bl0 = Kl[br + tig], bl1 = Kl[br + tig + 4];
                    mma_bf16(s[sub], qh[ks], bh0, bh1);
                    mma_bf16(s[sub], qh[ks], bl0, bl1);
                    mma_bf16(s[sub], ql[ks], bh0, bh1);
                }
            }

            if (kt >= 2*qt2) {
                const int rel = (kt - 2*qt2) * 64;
                #pragma unroll
                for (int sub = 0; sub < 8; ++sub) {
                    const int kc = sub * 8 + 2 * tig + rel;
                    const int r_lo = g0 + g, r_hi = r_lo + 8;
                    if (kc     > r_lo) s[sub][0] = -INFINITY;
                    if (kc + 1 > r_lo) s[sub][1] = -INFINITY;
                    if (kc     > r_hi) s[sub][2] = -INFINITY;
                    if (kc + 1 > r_hi) s[sub][3] = -INFINITY;
                }
            }

            float mt0 = -INFINITY, mt1 = -INFINITY;
            #pragma unroll
            for (int sub = 0; sub < 8; ++sub) {
                mt0 = fmaxf(mt0, fmaxf(s[sub][0], s[sub][1]));
                mt1 = fmaxf(mt1, fmaxf(s[sub][2], s[sub][3]));
            }
            mt0 = fmaxf(mt0, __shfl_xor_sync(0xffffffffu, mt0, 1));
            mt0 = fmaxf(mt0, __shfl_xor_sync(0xffffffffu, mt0, 2));
            mt1 = fmaxf(mt1, __shfl_xor_sync(0xffffffffu, mt1, 1));
            mt1 = fmaxf(mt1, __shfl_xor_sync(0xffffffffu, mt1, 2));

            const float mn0 = fmaxf(m0, mt0);
            const float mn1 = fmaxf(m1, mt1);
            const float c0f = __expf(m0 - mn0);
            const float c1f = __expf(m1 - mn1);

            unsigned ph[8][2], pl[8][2];
            float sum0 = 0.f, sum1 = 0.f;
            #pragma unroll
            for (int sub = 0; sub < 8; ++sub) {
                float p0 = __expf(s[sub][0] - mn0);
                float p1 = __expf(s[sub][1] - mn0);
                float p2 = __expf(s[sub][2] - mn1);
                float p3 = __expf(s[sub][3] - mn1);
                sum0 += p0 + p1;  sum1 += p2 + p3;
                split2(p0, p1, ph[sub][0], pl[sub][0]);
                split2(p2, p3, ph[sub][1], pl[sub][1]);
                o[sub][0] *= c0f; o[sub][1] *= c0f;
                o[sub][2] *= c1f; o[sub][3] *= c1f;
            }
            sum0 += __shfl_xor_sync(0xffffffffu, sum0, 1);
            sum0 += __shfl_xor_sync(0xffffffffu, sum0, 2);
            sum1 += __shfl_xor_sync(0xffffffffu, sum1, 1);
            sum1 += __shfl_xor_sync(0xffffffffu, sum1, 2);
            l0 = l0 * c0f + sum0;
            l1 = l1 * c1f + sum1;
            m0 = mn0; m1 = mn1;

            #pragma unroll
            for (int j = 0; j < 4; ++j) {
                unsigned ah[4] = {ph[2*j][0], ph[2*j][1], ph[2*j+1][0], ph[2*j+1][1]};
                unsigned al[4] = {pl[2*j][0], pl[2*j][1], pl[2*j+1][0], pl[2*j+1][1]};
                #pragma unroll
                for (int sub = 0; sub < 8; ++sub) {
                    const int br = (sub * 8 + g) * TSTRIDE + j * 8;
                    unsigned bh0 = Vh[br + tig], bh1 = Vh[br + tig + 4];
                    unsigned bl0 = Vl[br + tig], bl1 = Vl[br + tig + 4];
                    mma_bf16(o[sub], ah, bh0, bh1);
                    mma_bf16(o[sub], ah, bl0, bl1);
                    mma_bf16(o[sub], al, bh0, bh1);
                }
            }
        }
        __syncthreads();
    }

    // ---- write unnormalized partials ----
    const int slot = (b * NQT + qt2) * NCH + chunk;
    float* po = g_pO + (size_t)slot * 8192;
    #pragma unroll
    for (int sub = 0; sub < 8; ++sub) {
        const int dcol = sub * 8 + 2 * tig;
        *(float2*)&po[(g0 + g) * 64 + dcol]     = make_float2(o[sub][0], o[sub][1]);
        *(float2*)&po[(g0 + g + 8) * 64 + dcol] = make_float2(o[sub][2], o[sub][3]);
    }
    if (tig == 0) {
        g_pm[slot * 128 + g0 + g]     = m0;
        g_pm[slot * 128 + g0 + g + 8] = m1;
        g_pl[slot * 128 + g0 + g]     = l0;
        g_pl[slot * 128 + g0 + g + 8] = l1;
    }
}

// ---------------------------------------------------------------------------
// Kernel 3: merge split-KV partials.  grid = 512, block = 256.
// ---------------------------------------------------------------------------
__global__ __launch_bounds__(256)
void merge_kernel(float* __restrict__ out) {
    const int bq      = blockIdx.x >> 2;         // 0..127
    const int quarter = blockIdx.x & 3;
    const int b   = bq >> 5;
    const int qt2 = bq & 31;
    const int nch = (2 * qt2 + 17) >> 4;         // ceil((2*qt2+2)/16)
    const int base_slot = bq * NCH;

    for (int e = threadIdx.x; e < 2048; e += 256) {
        const int row = quarter * 32 + (e >> 6);
        const int col = e & 63;
        float M = -INFINITY;
        #pragma unroll
        for (int c = 0; c < NCH; ++c)
            if (c < nch) M = fmaxf(M, g_pm[(base_slot + c) * 128 + row]);
        float denom = 0.f, acc = 0.f;
        #pragma unroll
        for (int c = 0; c < NCH; ++c) {
            if (c < nch) {
                float w = __expf(g_pm[(base_slot + c) * 128 + row] - M);
                denom += w * g_pl[(base_slot + c) * 128 + row];
                acc   += w * g_pO[(size_t)(base_slot + c) * 8192 + row * 64 + col];
            }
        }
        out[((size_t)(b * LL + qt2 * 128 + row)) * 64 + col] = acc / denom;
    }
}

// ---------------------------------------------------------------------------
extern "C" void kernel_launch(void* const* d_in, const int* in_sizes, int n_in,
                              void* d_out, int out_size) {
    (void)in_sizes; (void)n_in; (void)out_size;
    const float* x  = (const float*)d_in[0];
    const float* Wq = (const float*)d_in[1];
    const float* Wk = (const float*)d_in[2];
    const float* Wv = (const float*)d_in[3];
    float* out = (float*)d_out;

    prepw_kernel<<<32, 256>>>(Wq, Wk, Wv);
    {
        dim3 grid(3, NROWS / 64);
        qkv_kernel<<<grid, 128>>>(x);
    }
    {
        size_t smem = (size_t)2 * 4 * TILE_U32 * sizeof(unsigned);  // 73728 B
        cudaFuncSetAttribute(attn_kernel, cudaFuncAttributeMaxDynamicSharedMemorySize, (int)smem);
        attn_kernel<<<320, 256, smem>>>();
    }
    merge_kernel<<<512, 256>>>(out);
}